// round 17
// baseline (speedup 1.0000x reference)
#include <cuda_runtime.h>
#include <cuda_fp16.h>
#include <math.h>
#include <stdint.h>

#define BATCH 16
#define CHN   640
#define SP    4096
#define TT    77
#define XDIM  768
#define NHE   8
#define HDIM  80
#define INNER 640
#define KVW   1280          // fused K|V width

// ---------------- scratch ----------------
__device__ __half g_q16  [(size_t)BATCH * SP * INNER];
__device__ __half g_kv16 [(size_t)BATCH * TT * KVW];    // [m][ K(640) | V(640) ]
__device__ __half g_x16  [(size_t)BATCH * SP * CHN];
__device__ __half g_at16 [(size_t)BATCH * SP * INNER];
__device__ __half g_e16  [(size_t)BATCH * TT * XDIM];
__device__ __half g_wq16 [(size_t)INNER * CHN];
__device__ __half g_wkv16[(size_t)KVW * XDIM];
__device__ __half g_wo16 [(size_t)CHN * INNER];

// ---------------- helpers ----------------
__device__ __forceinline__ uint32_t smem_u32(const void* p) {
    uint32_t a;
    asm("{ .reg .u64 t; cvta.to.shared.u64 t, %1; cvt.u32.u64 %0, t; }"
        : "=r"(a) : "l"(p));
    return a;
}
__device__ __forceinline__ void cp16(uint32_t dst, const void* src, bool v) {
    int sz = v ? 16 : 0;
    asm volatile("cp.async.cg.shared.global [%0], [%1], 16, %2;"
                 :: "r"(dst), "l"(src), "r"(sz) : "memory");
}
#define CP_COMMIT() asm volatile("cp.async.commit_group;" ::: "memory")
#define CP_WAIT1()  asm volatile("cp.async.wait_group 1;" ::: "memory")
#define CP_WAIT0()  asm volatile("cp.async.wait_group 0;" ::: "memory")

__device__ __forceinline__ void ldsm4(unsigned r[4], uint32_t a) {
    asm volatile("ldmatrix.sync.aligned.m8n8.x4.shared.b16 {%0,%1,%2,%3}, [%4];"
                 : "=r"(r[0]), "=r"(r[1]), "=r"(r[2]), "=r"(r[3]) : "r"(a));
}
__device__ __forceinline__ void ldsm4t(unsigned r[4], uint32_t a) {
    asm volatile("ldmatrix.sync.aligned.m8n8.x4.trans.shared.b16 {%0,%1,%2,%3}, [%4];"
                 : "=r"(r[0]), "=r"(r[1]), "=r"(r[2]), "=r"(r[3]) : "r"(a));
}

__device__ __forceinline__ void mma_f16(float c[4], unsigned a0, unsigned a1,
                                        unsigned a2, unsigned a3,
                                        unsigned b0, unsigned b1)
{
    asm volatile(
        "mma.sync.aligned.m16n8k16.row.col.f32.f16.f16.f32 "
        "{%0,%1,%2,%3},{%4,%5,%6,%7},{%8,%9},{%0,%1,%2,%3};"
        : "+f"(c[0]), "+f"(c[1]), "+f"(c[2]), "+f"(c[3])
        : "r"(a0), "r"(a1), "r"(a2), "r"(a3), "r"(b0), "r"(b1));
}

// ---------------- fused LN: stats + normalize + transpose in one pass ----------------
#define LN_TILE  (CHN * 33)
#define LN_SMEM  ((LN_TILE + 2 * 8 * 33 + 64) * 4)

__global__ void __launch_bounds__(256) ln_fused(const float* __restrict__ x,
                                                const float* __restrict__ lw,
                                                const float* __restrict__ lb)
{
    extern __shared__ float sm[];
    float* tile = sm;                  // [640][33]
    float* p1 = sm + LN_TILE;          // [8][33]
    float* p2 = p1 + 8 * 33;           // [8][33]
    float* mus = p2 + 8 * 33;          // [32]
    float* rss = mus + 32;             // [32]

    int tid = threadIdx.x, sl = tid & 31, wp = tid >> 5;
    int s0 = blockIdx.x * 32, b = blockIdx.y;

    const float* xb = x + (size_t)b * CHN * SP + s0;
#pragma unroll 8
    for (int it = 0; it < 80; it++) {
        int c = it * 8 + wp;
        tile[c * 33 + sl] = xb[(size_t)c * SP + sl];
    }
    __syncthreads();

    float sum = 0.f, sq = 0.f;
#pragma unroll 8
    for (int k = 0; k < 80; k++) {
        float v = tile[(wp + 8 * k) * 33 + sl];
        sum += v; sq += v * v;
    }
    p1[wp * 33 + sl] = sum;
    p2[wp * 33 + sl] = sq;
    __syncthreads();
    if (tid < 32) {
        float S = 0.f, Q = 0.f;
#pragma unroll
        for (int g = 0; g < 8; g++) { S += p1[g * 33 + tid]; Q += p2[g * 33 + tid]; }
        float mu = S * (1.0f / CHN);
        float var = Q * (1.0f / CHN) - mu * mu;
        mus[tid] = mu;
        rss[tid] = rsqrtf(var + 1e-6f);
    }
    __syncthreads();

    __half* ob = g_x16 + ((size_t)b * SP + s0) * CHN;
#pragma unroll 4
    for (int it = 0; it < 40; it++) {
        int idx = it * 256 + tid;
        int s = idx / 320, c = (idx - s * 320) * 2;
        float mu = mus[s], rs = rss[s];
        float v0 = (tile[c * 33 + s]       - mu) * rs * lw[c]     + lb[c];
        float v1 = (tile[(c + 1) * 33 + s] - mu) * rs * lw[c + 1] + lb[c + 1];
        *(__half2*)(ob + (size_t)s * CHN + c) = __floats2half2_rn(v0, v1);
    }
}

// ---------------- weight transpose+cvt ----------------
__global__ void __launch_bounds__(256) cvt_w_t(const float* __restrict__ in,
                                               __half* __restrict__ out, int R, int C)
{
    __shared__ float t[32][33];
    int c0 = blockIdx.x * 32, r0 = blockIdx.y * 32;
    int xl = threadIdx.x & 31, y = (threadIdx.x >> 5) * 4;
#pragma unroll
    for (int i = 0; i < 4; i++)
        t[y + i][xl] = in[(size_t)(r0 + y + i) * C + c0 + xl];
    __syncthreads();
#pragma unroll
    for (int i = 0; i < 4; i++)
        out[(size_t)(c0 + y + i) * R + r0 + xl] = __float2half_rn(t[xl][y + i]);
}

// ---------------- elementwise cvt ----------------
__global__ void __launch_bounds__(256) cvt16(const float* __restrict__ in,
                                             __half* __restrict__ out, int n)
{
    int i = blockIdx.x * 256 + threadIdx.x;
    if (i < n) out[i] = __float2half_rn(in[i]);
}

// ---------------- fp16 mma GEMM: D = A[M][K] * Bt[N][K]^T ----------------
#define HBOFF  10240
#define HSTG   20480
#define HGSMEM (3 * HSTG)

template<int EPI, bool MG>
__global__ void __launch_bounds__(256, 2)
gemm_h(const __half* __restrict__ A, const __half* __restrict__ Bt,
       void* __restrict__ CoutV, int M, int N, int K, int lda,
       const float* __restrict__ bias, const float* __restrict__ resid)
{
    extern __shared__ char smc[];
    uint32_t sb = smem_u32(smc);

    int tid = threadIdx.x, lane = tid & 31, w = tid >> 5;
    int r = lane >> 2, q = lane & 3;
    int wm = w & 3, wn = w >> 2;
    int m0 = blockIdx.y * 128;
    int n0 = blockIdx.x * 128;
    int mb = wm * 32, nb = wn * 64;
    int NT = K >> 5;

    uint32_t offA = (uint32_t)((mb + (lane & 15)) * 40 + ((lane & 16) ? 8 : 0)) * 2;
    uint32_t offB = (uint32_t)((nb + (lane & 7) + ((lane & 16) ? 8 : 0)) * 40
                               + ((lane & 8) ? 8 : 0)) * 2;

    float acc[2][8][4];
#pragma unroll
    for (int i = 0; i < 2; i++)
#pragma unroll
        for (int j = 0; j < 8; j++)
#pragma unroll
            for (int l = 0; l < 4; l++) acc[i][j][l] = 0.f;

    auto load_stage = [&](int slot, int k0) {
        uint32_t st = sb + slot * HSTG;
#pragma unroll
        for (int i = 0; i < 2; i++) {
            int cid = tid + i * 256;
            int row = cid >> 2, ch = cid & 3;
            bool v = !MG || (m0 + row) < M;
            cp16(st + row * 80 + ch * 16,
                 A + (size_t)(m0 + row) * lda + k0 + ch * 8, v);
        }
#pragma unroll
        for (int i = 0; i < 2; i++) {
            int cid = tid + i * 256;
            int row = cid >> 2, ch = cid & 3;
            cp16(st + HBOFF + row * 80 + ch * 16,
                 Bt + (size_t)(n0 + row) * K + k0 + ch * 8, true);
        }
    };

    load_stage(0, 0);  CP_COMMIT();
    load_stage(1, 32); CP_COMMIT();

    for (int t = 0; t < NT; t++) {
        if (t == NT - 1) CP_WAIT0(); else CP_WAIT1();
        __syncthreads();
        if (t + 2 < NT) { load_stage((t + 2) % 3, (t + 2) * 32); CP_COMMIT(); }

        int slot = t % 3;
        uint32_t aBase = sb + slot * HSTG + offA;
        uint32_t bBase = sb + slot * HSTG + HBOFF + offB;

        unsigned ac[2][4], an[2][4];
        ldsm4(ac[0], aBase);
        ldsm4(ac[1], aBase + 1280);
#pragma unroll
        for (int kc = 0; kc < 2; kc++) {
            if (kc == 0) {
                ldsm4(an[0], aBase + 32);
                ldsm4(an[1], aBase + 1280 + 32);
            }
            unsigned bb[4][4];
#pragma unroll
            for (int j = 0; j < 4; j++)
                ldsm4(bb[j], bBase + j * 1280 + kc * 32);
#pragma unroll
            for (int j = 0; j < 4; j++) {
#pragma unroll
                for (int im = 0; im < 2; im++)
                    mma_f16(acc[im][2 * j], ac[im][0], ac[im][1], ac[im][2],
                            ac[im][3], bb[j][0], bb[j][1]);
#pragma unroll
                for (int im = 0; im < 2; im++)
                    mma_f16(acc[im][2 * j + 1], ac[im][0], ac[im][1], ac[im][2],
                            ac[im][3], bb[j][2], bb[j][3]);
            }
            if (kc == 0) {
#pragma unroll
                for (int im = 0; im < 2; im++)
#pragma unroll
                    for (int jj = 0; jj < 4; jj++) ac[im][jj] = an[im][jj];
            }
        }
    }
    __syncthreads();

    // -------- epilogue --------
    float* Cs = (float*)smc;
    if (EPI != 1) {
#pragma unroll 1
        for (int ch = 0; ch < 4; ch++) {
            __syncthreads();
            if (wm == ch) {
#pragma unroll
                for (int im = 0; im < 2; im++) {
                    int r0 = im * 16 + r;
#pragma unroll
                    for (int in_ = 0; in_ < 8; in_++) {
                        int cc = nb + in_ * 8 + q * 2;
                        Cs[r0 * 132 + cc]           = acc[im][in_][0];
                        Cs[r0 * 132 + cc + 1]       = acc[im][in_][1];
                        Cs[(r0 + 8) * 132 + cc]     = acc[im][in_][2];
                        Cs[(r0 + 8) * 132 + cc + 1] = acc[im][in_][3];
                    }
                }
            }
            __syncthreads();
            for (int t = tid; t < 32 * 128; t += 256) {
                int ml = t >> 7, n = t & 127;
                int m = m0 + ch * 32 + ml;
                if (MG && m >= M) continue;
                if (EPI == 0)
                    ((float*)CoutV)[(size_t)m * N + n0 + n] = Cs[ml * 132 + n];
                else
                    ((__half*)CoutV)[(size_t)m * N + n0 + n] =
                        __float2half_rn(Cs[ml * 132 + n]);
            }
        }
    } else {
#pragma unroll 1
        for (int ch = 0; ch < 4; ch++) {
            __syncthreads();
            if (wn == (ch >> 1)) {
                int inlo = (ch & 1) * 4;
#pragma unroll
                for (int im = 0; im < 2; im++) {
                    int mrow = mb + im * 16 + r;
#pragma unroll
                    for (int ii = 0; ii < 4; ii++) {
                        int in_ = inlo + ii;
                        int nl = in_ * 8 + q * 2 - (ch & 1) * 32;
                        Cs[nl * 132 + mrow]           = acc[im][in_][0];
                        Cs[(nl + 1) * 132 + mrow]     = acc[im][in_][1];
                        Cs[nl * 132 + mrow + 8]       = acc[im][in_][2];
                        Cs[(nl + 1) * 132 + mrow + 8] = acc[im][in_][3];
                    }
                }
            }
            __syncthreads();
            for (int t = tid; t < 32 * 128; t += 256) {
                int nl = t >> 7, ml = t & 127;
                int n = n0 + ch * 32 + nl;
                int m = m0 + ml;
                int b = m >> 12, s = m & (SP - 1);
                size_t addr = (size_t)b * CHN * SP + (size_t)n * SP + s;
                ((float*)CoutV)[addr] = Cs[nl * 132 + ml] + bias[n] + resid[addr];
            }
        }
    }
}

// ---------------- fp16 tensor-core attention: 2 q-blocks per CTA ----------------
#define AT_SMEM 28160

__global__ void __launch_bounds__(256, 2) attn_mma()
{
    extern __shared__ __half smh[];
    __half* Kh = smh;            // [80][88]
    __half* Vh = smh + 7040;     // [80][88]

    int tid = threadIdx.x, lane = tid & 31, w = tid >> 5;
    int b = blockIdx.z, h = blockIdx.y;
    int mb = w * 16;
    int r = lane >> 2, q = lane & 3, q2 = q * 2;
    uint32_t sb = smem_u32(smh);

    const __half* kg = g_kv16 + (size_t)b * TT * KVW + h * HDIM;
    const __half* vg = kg + INNER;

    // stage K,V once per CTA
#pragma unroll
    for (int i = 0; i < 4; i++) {
        int cid = tid + i * 256;
        if (cid < 770) {
            int t = cid / 10, ch = cid % 10;
            cp16(sb + (t * 88 + ch * 8) * 2, kg + (size_t)t * KVW + ch * 8, true);
            cp16(sb + (7040 + t * 88 + ch * 8) * 2, vg + (size_t)t * KVW + ch * 8, true);
        }
    }
    CP_COMMIT();

    if (tid < 240) {
        int row = 77 + tid / 80, col = tid % 80;
        Kh[row * 88 + col] = __float2half(0.f);
        Vh[row * 88 + col] = __float2half(0.f);
    }
    CP_WAIT0();
    __syncthreads();

    uint32_t kBase = sb + (uint32_t)(((lane & 7) + ((lane & 16) ? 8 : 0)) * 88
                                     + ((lane & 8) ? 8 : 0)) * 2;
    uint32_t vBase = sb + 14080 + (uint32_t)(((lane & 7) + ((lane & 16) ? 8 : 0)) * 88) * 2
                   + (uint32_t)((lane & 8) ? 16 : 0);
    const float scale = 0.11180339887498949f;

#pragma unroll 1
    for (int qb = 0; qb < 2; qb++) {
        int q0 = blockIdx.x * 256 + qb * 128;

        const __half* qg = g_q16 + ((size_t)b * SP + q0 + mb) * INNER + h * HDIM;
        unsigned qf[5][4];
#pragma unroll
        for (int k8 = 0; k8 < 5; k8++) {
            int c = k8 * 16 + q2;
            qf[k8][0] = *(const unsigned*)(qg + (size_t)r * INNER + c);
            qf[k8][1] = *(const unsigned*)(qg + (size_t)(r + 8) * INNER + c);
            qf[k8][2] = *(const unsigned*)(qg + (size_t)r * INNER + c + 8);
            qf[k8][3] = *(const unsigned*)(qg + (size_t)(r + 8) * INNER + c + 8);
        }

        float acc[10][4];
#pragma unroll
        for (int i = 0; i < 10; i++)
#pragma unroll
            for (int j = 0; j < 4; j++) acc[i][j] = 0.f;

#pragma unroll
        for (int k8 = 0; k8 < 5; k8++) {
#pragma unroll
            for (int tp = 0; tp < 5; tp++) {
                unsigned bb[4];
                ldsm4(bb, kBase + tp * 2816 + k8 * 32);
                mma_f16(acc[2 * tp],     qf[k8][0], qf[k8][1], qf[k8][2], qf[k8][3],
                        bb[0], bb[1]);
                mma_f16(acc[2 * tp + 1], qf[k8][0], qf[k8][1], qf[k8][2], qf[k8][3],
                        bb[2], bb[3]);
            }
        }

        float invs[2];
#pragma unroll
        for (int hf = 0; hf < 2; hf++) {
            float mx = -1e30f;
#pragma unroll
            for (int in_ = 0; in_ < 10; in_++) {
                int c0 = in_ * 8 + q2;
                float v0 = (c0     < TT) ? acc[in_][hf * 2]     * scale : -1e30f;
                float v1 = (c0 + 1 < TT) ? acc[in_][hf * 2 + 1] * scale : -1e30f;
                acc[in_][hf * 2] = v0; acc[in_][hf * 2 + 1] = v1;
                mx = fmaxf(mx, fmaxf(v0, v1));
            }
            mx = fmaxf(mx, __shfl_xor_sync(0xffffffffu, mx, 1));
            mx = fmaxf(mx, __shfl_xor_sync(0xffffffffu, mx, 2));
            float s = 0.f;
#pragma unroll
            for (int in_ = 0; in_ < 10; in_++) {
                int c0 = in_ * 8 + q2;
                float e0 = (c0     < TT) ? __expf(acc[in_][hf * 2]     - mx) : 0.f;
                float e1 = (c0 + 1 < TT) ? __expf(acc[in_][hf * 2 + 1] - mx) : 0.f;
                acc[in_][hf * 2] = e0; acc[in_][hf * 2 + 1] = e1;
                s += e0 + e1;
            }
            s += __shfl_xor_sync(0xffffffffu, s, 1);
            s += __shfl_xor_sync(0xffffffffu, s, 2);
            invs[hf] = 1.f / s;
        }

        unsigned pf[5][4];
#pragma unroll
        for (int k8 = 0; k8 < 5; k8++) {
            __half2 h0 = __floats2half2_rn(acc[2 * k8][0],     acc[2 * k8][1]);
            __half2 h1 = __floats2half2_rn(acc[2 * k8][2],     acc[2 * k8][3]);
            __half2 h2 = __floats2half2_rn(acc[2 * k8 + 1][0], acc[2 * k8 + 1][1]);
            __half2 h3 = __floats2half2_rn(acc[2 * k8 + 1][2], acc[2 * k8 + 1][3]);
            pf[k8][0] = *(unsigned*)&h0;
            pf[k8][1] = *(unsigned*)&h1;
            pf[k8][2] = *(unsigned*)&h2;
            pf[k8][3] = *(unsigned*)&h3;
        }

        float oc[10][4];
#pragma unroll
        for (int i = 0; i < 10; i++)
#pragma unroll
            for (int j = 0; j < 4; j++) oc[i][j] = 0.f;

#pragma unroll
        for (int k8 = 0; k8 < 5; k8++) {
#pragma unroll
            for (int dp = 0; dp < 5; dp++) {
                unsigned vb[4];
                ldsm4t(vb, vBase + k8 * 2816 + dp * 32);
                mma_f16(oc[2 * dp],     pf[k8][0], pf[k8][1], pf[k8][2], pf[k8][3],
                        vb[0], vb[2]);
                mma_f16(oc[2 * dp + 1], pf[k8][0], pf[k8][1], pf[k8][2], pf[k8][3],
                        vb[1], vb[3]);
            }
        }

        __half* og = g_at16 + ((size_t)b * SP + q0 + mb) * INNER + h * HDIM;
#pragma unroll
        for (int in_ = 0; in_ < 10; in_++) {
            int c = in_ * 8 + q2;
            *(__half2*)(og + (size_t)r * INNER + c) =
                __floats2half2_rn(oc[in_][0] * invs[0], oc[in_][1] * invs[0]);
            *(__half2*)(og + (size_t)(r + 8) * INNER + c) =
                __floats2half2_rn(oc[in_][2] * invs[1], oc[in_][3] * invs[1]);
        }
    }
}

// ---------------- launch ----------------
extern "C" void kernel_launch(void* const* d_in, const int* in_sizes, int n_in,
                              void* d_out, int out_size)
{
    (void)in_sizes; (void)n_in; (void)out_size;
    const float* hs  = (const float*)d_in[0];
    const float* enc = (const float*)d_in[1];
    const float* lnw = (const float*)d_in[2];
    const float* lnb = (const float*)d_in[3];
    const float* wq  = (const float*)d_in[4];
    const float* wk  = (const float*)d_in[5];
    const float* wv  = (const float*)d_in[6];
    const float* wo  = (const float*)d_in[7];
    const float* bo  = (const float*)d_in[8];
    float* out = (float*)d_out;

    __half *p_q16, *p_kv16, *p_x16, *p_at16, *p_e16;
    __half *p_wq16, *p_wkv16, *p_wo16;
    cudaGetSymbolAddress((void**)&p_q16,   g_q16);
    cudaGetSymbolAddress((void**)&p_kv16,  g_kv16);
    cudaGetSymbolAddress((void**)&p_x16,   g_x16);
    cudaGetSymbolAddress((void**)&p_at16,  g_at16);
    cudaGetSymbolAddress((void**)&p_e16,   g_e16);
    cudaGetSymbolAddress((void**)&p_wq16,  g_wq16);
    cudaGetSymbolAddress((void**)&p_wkv16, g_wkv16);
    cudaGetSymbolAddress((void**)&p_wo16,  g_wo16);

    static cudaStream_t s1 = nullptr;
    static cudaEvent_t evF = nullptr, evQ = nullptr, evJ = nullptr;
    if (s1 == nullptr) {
        cudaStreamCreateWithFlags(&s1, cudaStreamNonBlocking);
        cudaEventCreateWithFlags(&evF, cudaEventDisableTiming);
        cudaEventCreateWithFlags(&evQ, cudaEventDisableTiming);
        cudaEventCreateWithFlags(&evJ, cudaEventDisableTiming);
        cudaFuncSetAttribute(gemm_h<2, false>,
                             cudaFuncAttributeMaxDynamicSharedMemorySize, HGSMEM);
        cudaFuncSetAttribute(gemm_h<2, true>,
                             cudaFuncAttributeMaxDynamicSharedMemorySize, HGSMEM);
        cudaFuncSetAttribute(gemm_h<1, false>,
                             cudaFuncAttributeMaxDynamicSharedMemorySize, HGSMEM);
        cudaFuncSetAttribute(attn_mma,
                             cudaFuncAttributeMaxDynamicSharedMemorySize, AT_SMEM);
        cudaFuncSetAttribute(ln_fused,
                             cudaFuncAttributeMaxDynamicSharedMemorySize, LN_SMEM);
    }

    // fork: stream B handles ALL weight cvts + enc cvt + fused KV GEMM
    cudaEventRecord(evF, 0);
    cudaStreamWaitEvent(s1, evF, 0);

    // wq first — Q GEMM (stream A) only needs this from stream B
    cvt_w_t<<<dim3(INNER / 32, CHN / 32), 256, 0, s1>>>(wq, p_wq16, CHN, INNER);
    cudaEventRecord(evQ, s1);
    cvt_w_t<<<dim3(INNER / 32, XDIM / 32), 256, 0, s1>>>(wk, p_wkv16, XDIM, INNER);
    cvt_w_t<<<dim3(INNER / 32, XDIM / 32), 256, 0, s1>>>(
        wv, p_wkv16 + (size_t)INNER * XDIM, XDIM, INNER);
    cvt_w_t<<<dim3(CHN / 32, INNER / 32), 256, 0, s1>>>(wo, p_wo16, INNER, CHN);
    {
        int n = BATCH * TT * XDIM;
        cvt16<<<(n + 255) / 256, 256, 0, s1>>>(enc, p_e16, n);
    }
    gemm_h<2, true><<<dim3(KVW / 128, (BATCH * TT + 127) / 128), 256, HGSMEM, s1>>>(
        p_e16, p_wkv16, p_kv16, BATCH * TT, KVW, XDIM, XDIM, nullptr, nullptr);
    cudaEventRecord(evJ, s1);

    // --- stream A (default): fused LN immediately, then Q GEMM (waits wq cvt) ---
    ln_fused<<<dim3(SP / 32, BATCH), 256, LN_SMEM>>>(hs, lnw, lnb);
    cudaStreamWaitEvent(0, evQ, 0);
    gemm_h<2, false><<<dim3(INNER / 128, (BATCH * SP) / 128), 256, HGSMEM>>>(
        p_x16, p_wq16, p_q16, BATCH * SP, INNER, CHN, CHN, nullptr, nullptr);

    // join KV chain
    cudaStreamWaitEvent(0, evJ, 0);

    // attention (fp16 tensor-core, 2 q-blocks per CTA)
    attn_mma<<<dim3(SP / 256, NHE, BATCH), 256, AT_SMEM>>>();

    // out = at16 @ wo16^T + bo + residual (transposed store, fp32)
    gemm_h<1, false><<<dim3(CHN / 128, (BATCH * SP) / 128), 256, HGSMEM>>>(
        p_at16, p_wo16, out, BATCH * SP, CHN, INNER, INNER, bo, hs);
}